// round 2
// baseline (speedup 1.0000x reference)
#include <cuda_runtime.h>
#include <cstdint>

// GPUBatchProcessor: per-batch 4x4 homogeneous transform of positions +
// 3x3 rotation + renormalization of normals.
//
// Inputs (metadata order):
//   d_in[0]: batch_vertices  float32 [B, N, 6]
//   d_in[1]: batch_indices   int32   [B, M, 3]   (UNUSED by reference output)
//   d_in[2]: batch_transforms float32 [B, 4, 4]
// Output: float32 [B, N, 6]
//
// Pure HBM streaming. 4 vertices = 6 float4 per thread, front-batched
// streaming loads (__ldcs) + streaming stores (__stcs), 32-bit indexing.

static constexpr int BATCH = 8;
static constexpr int NVERT = 1000000;
static constexpr int QUADS = NVERT / 4;             // 250000 per batch
static constexpr int F4_PER_BATCH = NVERT * 6 / 4;  // 1,500,000 float4 per batch

__device__ __forceinline__ void xform_one(
    float x, float y, float z, float nx, float ny, float nz,
    const float m[16],
    float& px, float& py, float& pz, float& ox, float& oy, float& oz)
{
    float tx = fmaf(m[0], x, fmaf(m[1], y, fmaf(m[2], z, m[3])));
    float ty = fmaf(m[4], x, fmaf(m[5], y, fmaf(m[6], z, m[7])));
    float tz = fmaf(m[8], x, fmaf(m[9], y, fmaf(m[10], z, m[11])));
    float tw = fmaf(m[12], x, fmaf(m[13], y, fmaf(m[14], z, m[15])));
    float rw = __frcp_rn(tw);
    px = tx * rw; py = ty * rw; pz = tz * rw;

    float ux = fmaf(m[0], nx, fmaf(m[1], ny, m[2] * nz));
    float uy = fmaf(m[4], nx, fmaf(m[5], ny, m[6] * nz));
    float uz = fmaf(m[8], nx, fmaf(m[9], ny, m[10] * nz));
    float ss = fmaf(ux, ux, fmaf(uy, uy, uz * uz));
    float len = fmaxf(sqrtf(ss), 1e-8f);
    float inv = __frcp_rn(len);
    ox = ux * inv; oy = uy * inv; oz = uz * inv;
}

__global__ void __launch_bounds__(256)
batch_xform_kernel(const float4* __restrict__ verts,
                   const float* __restrict__ transforms,
                   float4* __restrict__ out)
{
    int quad = blockIdx.x * blockDim.x + threadIdx.x;
    if (quad >= QUADS) return;
    int b = blockIdx.y;

    // 16 warp-uniform matrix coefficients -> L1 broadcast, cached
    const float* T = transforms + b * 16;
    float m[16];
#pragma unroll
    for (int i = 0; i < 16; ++i) m[i] = __ldg(T + i);

    int base = b * F4_PER_BATCH + quad * 6;   // max ~12M, fits in int32

    // Front-batched streaming loads: 6 LDG.128.CS in flight
    float4 v0 = __ldcs(verts + base + 0);
    float4 v1 = __ldcs(verts + base + 1);
    float4 v2 = __ldcs(verts + base + 2);
    float4 v3 = __ldcs(verts + base + 3);
    float4 v4 = __ldcs(verts + base + 4);
    float4 v5 = __ldcs(verts + base + 5);

    // vertex 0: pos(v0.x,v0.y,v0.z)  nrm(v0.w,v1.x,v1.y)
    // vertex 1: pos(v1.z,v1.w,v2.x)  nrm(v2.y,v2.z,v2.w)
    // vertex 2: pos(v3.x,v3.y,v3.z)  nrm(v3.w,v4.x,v4.y)
    // vertex 3: pos(v4.z,v4.w,v5.x)  nrm(v5.y,v5.z,v5.w)
    float p0x,p0y,p0z,n0x,n0y,n0z;
    float p1x,p1y,p1z,n1x,n1y,n1z;
    float p2x,p2y,p2z,n2x,n2y,n2z;
    float p3x,p3y,p3z,n3x,n3y,n3z;
    xform_one(v0.x,v0.y,v0.z, v0.w,v1.x,v1.y, m, p0x,p0y,p0z, n0x,n0y,n0z);
    xform_one(v1.z,v1.w,v2.x, v2.y,v2.z,v2.w, m, p1x,p1y,p1z, n1x,n1y,n1z);
    xform_one(v3.x,v3.y,v3.z, v3.w,v4.x,v4.y, m, p2x,p2y,p2z, n2x,n2y,n2z);
    xform_one(v4.z,v4.w,v5.x, v5.y,v5.z,v5.w, m, p3x,p3y,p3z, n3x,n3y,n3z);

    __stcs(out + base + 0, make_float4(p0x,p0y,p0z,n0x));
    __stcs(out + base + 1, make_float4(n0y,n0z,p1x,p1y));
    __stcs(out + base + 2, make_float4(p1z,n1x,n1y,n1z));
    __stcs(out + base + 3, make_float4(p2x,p2y,p2z,n2x));
    __stcs(out + base + 4, make_float4(n2y,n2z,p3x,p3y));
    __stcs(out + base + 5, make_float4(p3z,n3x,n3y,n3z));
}

extern "C" void kernel_launch(void* const* d_in, const int* in_sizes, int n_in,
                              void* d_out, int out_size)
{
    const float4* verts = (const float4*)d_in[0];
    const float* transforms = (const float*)d_in[2];
    float4* out = (float4*)d_out;

    dim3 block(256);
    dim3 grid((QUADS + 255) / 256, BATCH);
    batch_xform_kernel<<<grid, block>>>(verts, transforms, out);
}